// round 6
// baseline (speedup 1.0000x reference)
#include <cuda_runtime.h>
#include <cstddef>
#include <cstdint>

#define BATCH     131072
#define N_FACTORS 64
#define RATING_LO 1.0f
#define RATING_HI 5.0f

#define ROWS_PER_BLOCK 32           // 8 warps x 4 rows
#define FEAT_FLOATS    (ROWS_PER_BLOCK * 2 * N_FACTORS)   // 4096 floats = 16KB

__device__ __forceinline__ void cp_async16(uint32_t smem_dst, const void* gmem_src) {
    asm volatile("cp.async.cg.shared.global [%0], [%1], 16;"
                 :: "r"(smem_dst), "l"(gmem_src) : "memory");
}

// Per block: 32 batch rows. LDGSTS gathers p/q rows directly into an smem tile
// shaped exactly like the output feature block; dot products via LDS.128;
// one cp.async.bulk pushes the 16KB tile to gmem (bypassing LSU/L1tex stores).
__global__ __launch_bounds__(256, 8)
void svd_predict_kernel(const int2*  __restrict__ user_item,   // [BATCH]
                        const float* __restrict__ pu,          // [N_USERS, 64]
                        const float* __restrict__ qi,          // [N_ITEMS, 64]
                        const float* __restrict__ bu,
                        const float* __restrict__ bi,
                        const float* __restrict__ gmean,
                        float*       __restrict__ out)         // [BATCH] ++ [BATCH,128]
{
    __shared__ __align__(1024) float feat[FEAT_FLOATS];

    const int tid  = threadIdx.x;
    const int w    = tid >> 5;
    const int lane = tid & 31;
    const int half = lane >> 4;        // which row of the pair this half-warp serves
    const int hl   = lane & 15;        // float4 index within a 64-float vector

    const int rA = 4 * w + half;       // rows within block: 4w+half and 4w+2+half
    const int rB = rA + 2;
    const int gbase = blockIdx.x * ROWS_PER_BLOCK;

    const int2 uiA = __ldg(&user_item[gbase + rA]);
    const int2 uiB = __ldg(&user_item[gbase + rB]);

    // smem destinations: feat[row][0:64] = p, feat[row][64:128] = q (output layout)
    const uint32_t sA = (uint32_t)__cvta_generic_to_shared(&feat[rA * 128 + hl * 4]);
    const uint32_t sB = (uint32_t)__cvta_generic_to_shared(&feat[rB * 128 + hl * 4]);

    cp_async16(sA,       pu + (size_t)uiA.x * N_FACTORS + hl * 4);
    cp_async16(sA + 256, qi + (size_t)uiA.y * N_FACTORS + hl * 4);
    cp_async16(sB,       pu + (size_t)uiB.x * N_FACTORS + hl * 4);
    cp_async16(sB + 256, qi + (size_t)uiB.y * N_FACTORS + hl * 4);
    asm volatile("cp.async.commit_group;" ::: "memory");
    asm volatile("cp.async.wait_group 0;" ::: "memory");
    __syncwarp();

    // Dot products from smem (writer lane == reader lane; conflict-free LDS.128)
    const float4* fA = (const float4*)&feat[rA * 128];
    const float4* fB = (const float4*)&feat[rB * 128];
    const float4 pa = fA[hl], qa = fA[16 + hl];
    const float4 pb = fB[hl], qb = fB[16 + hl];

    float dA = pa.x * qa.x + pa.y * qa.y + pa.z * qa.z + pa.w * qa.w;
    float dB = pb.x * qb.x + pb.y * qb.y + pb.z * qb.z + pb.w * qb.w;
    #pragma unroll
    for (int off = 8; off > 0; off >>= 1) {
        dA += __shfl_xor_sync(0xFFFFFFFFu, dA, off);
        dB += __shfl_xor_sync(0xFFFFFFFFu, dB, off);
    }

    if (hl == 0) {   // lanes 0 & 16: two predicts each (tiny, direct STG)
        const float g = __ldg(gmean);
        float prA = g + __ldg(&bu[uiA.x]) + __ldg(&bi[uiA.y]) + dA;
        float prB = g + __ldg(&bu[uiB.x]) + __ldg(&bi[uiB.y]) + dB;
        out[gbase + rA] = fminf(fmaxf(prA, RATING_LO), RATING_HI);
        out[gbase + rB] = fminf(fmaxf(prB, RATING_LO), RATING_HI);
    }

    // All copies complete block-wide, then one bulk store of the feature tile.
    __syncthreads();
    if (tid == 0) {
        asm volatile("fence.proxy.async.shared::cta;" ::: "memory");
        float* gdst = out + BATCH + (size_t)gbase * (2 * N_FACTORS);
        const uint32_t ssrc = (uint32_t)__cvta_generic_to_shared(feat);
        asm volatile("cp.async.bulk.global.shared::cta.bulk_group [%0], [%1], %2;"
                     :: "l"(gdst), "r"(ssrc), "r"(FEAT_FLOATS * 4) : "memory");
        asm volatile("cp.async.bulk.commit_group;" ::: "memory");
        asm volatile("cp.async.bulk.wait_group 0;" ::: "memory");
    }
}

extern "C" void kernel_launch(void* const* d_in, const int* in_sizes, int n_in,
                              void* d_out, int out_size)
{
    const int2*  user_item = (const int2*) d_in[0];
    const float* pu        = (const float*)d_in[1];
    const float* qi        = (const float*)d_in[2];
    const float* bu        = (const float*)d_in[3];
    const float* bi        = (const float*)d_in[4];
    const float* gmean     = (const float*)d_in[5];
    float*       out       = (float*)d_out;

    const int blocks = BATCH / ROWS_PER_BLOCK;   // 4096
    svd_predict_kernel<<<blocks, 256>>>(user_item, pu, qi, bu, bi, gmean, out);
}

// round 15
// speedup vs baseline: 1.1047x; 1.1047x over previous
#include <cuda_runtime.h>
#include <cstddef>

#define BATCH     131072
#define N_FACTORS 64
#define RATING_LO 1.0f
#define RATING_HI 5.0f

// 8 batch rows per warp. Half-warp owns one row of each pair (row = base + 2j + half);
// float4 lanes: one LDG.128 gathers a 64-float row-half for TWO rows at once.
// 8 independent 128-bit gathers in flight per warp (MLP=8).
__global__ __launch_bounds__(256)
void svd_predict_kernel(const int2*  __restrict__ user_item,   // [BATCH] (uid, iid)
                        const float* __restrict__ pu,          // [N_USERS, 64]
                        const float* __restrict__ qi,          // [N_ITEMS, 64]
                        const float* __restrict__ bu,
                        const float* __restrict__ bi,
                        const float* __restrict__ gmean,
                        float*       __restrict__ out)         // [BATCH] ++ [BATCH,128]
{
    const int warp_id = (blockIdx.x * blockDim.x + threadIdx.x) >> 5;
    const int lane    = threadIdx.x & 31;
    const int half    = lane >> 4;      // row parity within each pair
    const int hl      = lane & 15;      // float4 index within a 64-float row
    const int base    = warp_id * 8;

    // 4 broadcast int4 loads cover 8 (uid,iid) pairs.
    const int4* ui4 = (const int4*)(user_item + base);
    const int4 w0 = __ldg(ui4 + 0);   // rows base+0, base+1
    const int4 w1 = __ldg(ui4 + 1);   // rows base+2, base+3
    const int4 w2 = __ldg(ui4 + 2);
    const int4 w3 = __ldg(ui4 + 3);

    int uid[4], iid[4];
    uid[0] = half ? w0.z : w0.x;  iid[0] = half ? w0.w : w0.y;
    uid[1] = half ? w1.z : w1.x;  iid[1] = half ? w1.w : w1.y;
    uid[2] = half ? w2.z : w2.x;  iid[2] = half ? w2.w : w2.y;
    uid[3] = half ? w3.z : w3.x;  iid[3] = half ? w3.w : w3.y;

    // 8 independent 128-bit gathers.
    float4 p[4], q[4];
    #pragma unroll
    for (int j = 0; j < 4; j++) {
        p[j] = __ldg((const float4*)(pu + (size_t)uid[j] * N_FACTORS) + hl);
        q[j] = __ldg((const float4*)(qi + (size_t)iid[j] * N_FACTORS) + hl);
    }

    float d[4];
    #pragma unroll
    for (int j = 0; j < 4; j++)
        d[j] = p[j].x * q[j].x + p[j].y * q[j].y + p[j].z * q[j].z + p[j].w * q[j].w;
    #pragma unroll
    for (int off = 8; off > 0; off >>= 1) {     // xor<=8 keeps half-warps independent
        #pragma unroll
        for (int j = 0; j < 4; j++)
            d[j] += __shfl_xor_sync(0xFFFFFFFFu, d[j], off);
    }

    // Feature writes: streaming (write-once) to keep L2 for the factor tables.
    #pragma unroll
    for (int j = 0; j < 4; j++) {
        const int row = base + 2 * j + half;
        float* f = out + BATCH + (size_t)row * (2 * N_FACTORS);
        __stcs((float4*)f + hl,               p[j]);
        __stcs((float4*)(f + N_FACTORS) + hl, q[j]);
    }

    if (hl == 0) {   // lanes 0 & 16: four predicts each
        const float g = __ldg(gmean);
        #pragma unroll
        for (int j = 0; j < 4; j++) {
            const int row = base + 2 * j + half;
            float pr = g + __ldg(&bu[uid[j]]) + __ldg(&bi[iid[j]]) + d[j];
            out[row] = fminf(fmaxf(pr, RATING_LO), RATING_HI);
        }
    }
}

extern "C" void kernel_launch(void* const* d_in, const int* in_sizes, int n_in,
                              void* d_out, int out_size)
{
    const int2*  user_item = (const int2*) d_in[0];
    const float* pu        = (const float*)d_in[1];
    const float* qi        = (const float*)d_in[2];
    const float* bu        = (const float*)d_in[3];
    const float* bi        = (const float*)d_in[4];
    const float* gmean     = (const float*)d_in[5];
    float*       out       = (float*)d_out;

    const int threads        = 256;                 // 8 warps
    const int rows_per_block = (threads / 32) * 8;  // 64 rows per block
    const int blocks         = BATCH / rows_per_block;  // 2048
    svd_predict_kernel<<<blocks, threads>>>(user_item, pu, qi, bu, bi, gmean, out);
}